// round 7
// baseline (speedup 1.0000x reference)
#include <cuda_runtime.h>
#include <cuda_bf16.h>
#include <math.h>

#define BDIM   64
#define LDIM   1024
#define INDIM  512
#define HDIM   512
#define G3     1536
#define NCTA   128
#define HS     8

typedef unsigned long long u64;

// ---------- static device scratch (no allocations) ----------
__device__ float g_gx[(size_t)2 * BDIM * LDIM * G3];          // [dir][b][l][1536] fp32
__device__ __nv_bfloat16 g_xb[(size_t)BDIM * LDIM * 1536];    // A' = [hi|hi|lo]
__device__ __nv_bfloat16 g_wb[(size_t)2 * 1536 * 1536];       // B' = [hi|lo|hi] per dir
__device__ float g_h[2 * 2 * HDIM * BDIM];                    // [dir][buf][j][b]
__device__ unsigned g_ticket;                                 // monotonic barrier counter

// =====================================================================
// bf16 hi/lo split helpers (POD only, no unions)
// =====================================================================
__device__ __forceinline__ unsigned pack_bf16x2(float a, float b)
{
    unsigned lo = (unsigned)__bfloat16_as_ushort(__float2bfloat16(a));
    unsigned hi = (unsigned)__bfloat16_as_ushort(__float2bfloat16(b));
    return lo | (hi << 16);
}
__device__ __forceinline__ float bf16_hi(float v)
{
    return __bfloat162float(__float2bfloat16(v));
}

__global__ void convx_kernel(const float* __restrict__ X)
{
    const size_t i = (size_t)blockIdx.x * 256 + threadIdx.x;   // < 8388608
    float4 v = ((const float4*)X)[i];
    const size_t m  = i >> 7;
    const int    kq = (int)(i & 127);
    uint2 h, l;
    h.x = pack_bf16x2(v.x, v.y);
    h.y = pack_bf16x2(v.z, v.w);
    l.x = pack_bf16x2(v.x - bf16_hi(v.x), v.y - bf16_hi(v.y));
    l.y = pack_bf16x2(v.z - bf16_hi(v.z), v.w - bf16_hi(v.w));
    __nv_bfloat16* d = g_xb + m * 1536 + kq * 4;
    *(uint2*)(d)        = h;   // seg0: hi
    *(uint2*)(d + 512)  = h;   // seg1: hi
    *(uint2*)(d + 1024) = l;   // seg2: lo
}

__global__ void convw_kernel(const float* __restrict__ Wlr, const float* __restrict__ Wrl)
{
    const int i   = blockIdx.x * 256 + threadIdx.x;            // < 393216
    const int dir = i / 196608;
    const int rem = i - dir * 196608;
    const int n   = rem >> 7;
    const int kq  = rem & 127;
    const float* W = dir ? Wrl : Wlr;
    float4 v = ((const float4*)W)[rem];
    uint2 h, l;
    h.x = pack_bf16x2(v.x, v.y);
    h.y = pack_bf16x2(v.z, v.w);
    l.x = pack_bf16x2(v.x - bf16_hi(v.x), v.y - bf16_hi(v.y));
    l.y = pack_bf16x2(v.z - bf16_hi(v.z), v.w - bf16_hi(v.w));
    __nv_bfloat16* d = g_wb + (size_t)dir * 1536 * 1536 + (size_t)n * 1536 + kq * 4;
    *(uint2*)(d)        = h;   // seg0: hi
    *(uint2*)(d + 512)  = l;   // seg1: lo
    *(uint2*)(d + 1024) = h;   // seg2: hi
}

// =====================================================================
// bf16 tensor-core GEMM: C[m,n] = sum_k A'[m,k]*B'[n,k] + bias[n]
// M=65536, N=1536 (per dir), K'=1536. 128x128 tile, Ktile=32, 256 thr.
// Warps 4(M)x2(N), warp tile 32x64, mma.sync m16n8k16 bf16 row.col.
// =====================================================================
__device__ __forceinline__ void ldsm4(unsigned& r0, unsigned& r1, unsigned& r2, unsigned& r3,
                                      const void* p)
{
    unsigned a = (unsigned)__cvta_generic_to_shared(p);
    asm volatile("ldmatrix.sync.aligned.m8n8.x4.shared.b16 {%0,%1,%2,%3}, [%4];"
                 : "=r"(r0), "=r"(r1), "=r"(r2), "=r"(r3) : "r"(a));
}

__device__ __forceinline__ void mma16816(float* c, const unsigned* a, unsigned b0, unsigned b1)
{
    asm volatile("mma.sync.aligned.m16n8k16.row.col.f32.bf16.bf16.f32 "
                 "{%0,%1,%2,%3}, {%4,%5,%6,%7}, {%8,%9}, {%0,%1,%2,%3};"
                 : "+f"(c[0]), "+f"(c[1]), "+f"(c[2]), "+f"(c[3])
                 : "r"(a[0]), "r"(a[1]), "r"(a[2]), "r"(a[3]), "r"(b0), "r"(b1));
}

__global__ void __launch_bounds__(256, 1)
hgemm_kernel(const float* __restrict__ blr, const float* __restrict__ brl)
{
    __shared__ __nv_bfloat16 As[2][128][40];
    __shared__ __nv_bfloat16 Bs[2][128][40];

    const int tid  = threadIdx.x;
    const int lane = tid & 31;
    const int wid  = tid >> 5;
    const int dir  = blockIdx.z;
    const int m0   = blockIdx.y * 128;
    const int n0   = blockIdx.x * 128;
    const int wm   = wid >> 1;
    const int wn   = wid & 1;

    const int row0 = tid >> 2;          // 0..63
    const int cc   = tid & 3;

    const __nv_bfloat16* ga0 = g_xb + (size_t)(m0 + row0) * 1536 + cc * 8;
    const __nv_bfloat16* gb0 = g_wb + (size_t)dir * 1536 * 1536
                                    + (size_t)(n0 + row0) * 1536 + cc * 8;

    uint4 av0 = *(const uint4*)ga0;
    uint4 av1 = *(const uint4*)(ga0 + (size_t)64 * 1536);
    uint4 bv0 = *(const uint4*)gb0;
    uint4 bv1 = *(const uint4*)(gb0 + (size_t)64 * 1536);
    *(uint4*)&As[0][row0][cc * 8]      = av0;
    *(uint4*)&As[0][row0 + 64][cc * 8] = av1;
    *(uint4*)&Bs[0][row0][cc * 8]      = bv0;
    *(uint4*)&Bs[0][row0 + 64][cc * 8] = bv1;
    __syncthreads();

    float acc[2][8][4];
    #pragma unroll
    for (int mt = 0; mt < 2; ++mt)
        #pragma unroll
        for (int nt = 0; nt < 8; ++nt)
            #pragma unroll
            for (int q = 0; q < 4; ++q) acc[mt][nt][q] = 0.0f;

    #pragma unroll 1
    for (int kt = 0; kt < 48; ++kt) {
        const int buf = kt & 1;
        if (kt < 47) {
            const int off = (kt + 1) * 32;
            av0 = *(const uint4*)(ga0 + off);
            av1 = *(const uint4*)(ga0 + (size_t)64 * 1536 + off);
            bv0 = *(const uint4*)(gb0 + off);
            bv1 = *(const uint4*)(gb0 + (size_t)64 * 1536 + off);
        }
        #pragma unroll
        for (int ks = 0; ks < 2; ++ks) {
            unsigned af[2][4], bfr[4][4];
            #pragma unroll
            for (int mt = 0; mt < 2; ++mt)
                ldsm4(af[mt][0], af[mt][1], af[mt][2], af[mt][3],
                      &As[buf][wm * 32 + mt * 16 + (lane & 15)][ks * 16 + (lane >> 4) * 8]);
            #pragma unroll
            for (int nt2 = 0; nt2 < 4; ++nt2)
                ldsm4(bfr[nt2][0], bfr[nt2][1], bfr[nt2][2], bfr[nt2][3],
                      &Bs[buf][wn * 64 + nt2 * 16 + (lane & 15)][ks * 16 + (lane >> 4) * 8]);
            #pragma unroll
            for (int mt = 0; mt < 2; ++mt)
                #pragma unroll
                for (int nt = 0; nt < 8; ++nt)
                    mma16816(acc[mt][nt], af[mt],
                             bfr[nt >> 1][nt & 1], bfr[nt >> 1][2 + (nt & 1)]);
        }
        if (kt < 47) {
            const int nb = buf ^ 1;
            *(uint4*)&As[nb][row0][cc * 8]      = av0;
            *(uint4*)&As[nb][row0 + 64][cc * 8] = av1;
            *(uint4*)&Bs[nb][row0][cc * 8]      = bv0;
            *(uint4*)&Bs[nb][row0 + 64][cc * 8] = bv1;
        }
        __syncthreads();
    }

    const float* bia = dir ? brl : blr;
    float* C = g_gx + (size_t)dir * ((size_t)BDIM * LDIM * G3);
    #pragma unroll
    for (int mt = 0; mt < 2; ++mt) {
        #pragma unroll
        for (int nt = 0; nt < 8; ++nt) {
            const int r  = m0 + wm * 32 + mt * 16 + (lane >> 2);
            const int nc = n0 + wn * 64 + nt * 8 + (lane & 3) * 2;
            const float bx = bia[nc], by = bia[nc + 1];
            float* Cp = C + (size_t)r * G3 + nc;
            *(float2*)Cp = make_float2(acc[mt][nt][0] + bx, acc[mt][nt][1] + by);
            *(float2*)(Cp + (size_t)8 * G3) =
                make_float2(acc[mt][nt][2] + bx, acc[mt][nt][3] + by);
        }
    }
}

// =====================================================================
// Kernel 2: persistent recurrent scan with packed fma.rn.f32x2.
// =====================================================================
// SMEM floats: Ws2[24][512] float2 | hs[2][8192] | gxs[1536] | outs[512]
#define SM_WS     0
#define SM_HS     24576
#define SM_GXS    40960
#define SM_OUTS   42496
#define SM_FLOATS 43008

__device__ __forceinline__ void fma2(u64& acc, u64 a, u64 b)
{
    asm("fma.rn.f32x2 %0, %1, %2, %0;" : "+l"(acc) : "l"(a), "l"(b));
}
__device__ __forceinline__ u64 pack2(float x)
{
    unsigned r = __float_as_uint(x);
    u64 d;
    asm("mov.b64 %0, {%1, %2};" : "=l"(d) : "r"(r), "r"(r));
    return d;
}
__device__ __forceinline__ float2 unpack2(u64 d)
{
    unsigned lo, hi;
    asm("mov.b64 {%0, %1}, %2;" : "=r"(lo), "=r"(hi) : "l"(d));
    return make_float2(__uint_as_float(lo), __uint_as_float(hi));
}

__device__ __forceinline__ void grid_barrier()
{
    __syncthreads();
    if (threadIdx.x == 0) {
        __threadfence();
        unsigned t = atomicAdd(&g_ticket, 1u);
        unsigned target = (t / NCTA + 1u) * NCTA;
        while ((int)(*(volatile unsigned*)&g_ticket - target) < 0) { }
        __threadfence();
    }
    __syncthreads();
}

__device__ __forceinline__ float sigf(float x) { return 1.0f / (1.0f + __expf(-x)); }

__global__ void __launch_bounds__(256, 1)
scan_kernel(const float* __restrict__ feats_mask,
            const float* __restrict__ whh_lr, const float* __restrict__ bhh_lr,
            const float* __restrict__ whh_rl, const float* __restrict__ bhh_rl,
            float* __restrict__ out)
{
    extern __shared__ float sm[];
    float2* ws2  = (float2*)(sm + SM_WS);
    float*  hsS  = sm + SM_HS;
    float*  gxs  = sm + SM_GXS;
    float*  outs = sm + SM_OUTS;

    const int tid   = threadIdx.x;
    const int dir   = blockIdx.x >> 6;
    const int slice = blockIdx.x & 63;
    const int j0    = slice * HS;
    const int rg    = tid >> 5;
    const int bg    = tid & 31;
    const int b0    = 2 * bg;

    const float* __restrict__ whh = dir ? whh_rl : whh_lr;
    const float* __restrict__ bhh = dir ? bhh_rl : bhh_lr;
    const float* __restrict__ gxbase = g_gx + (size_t)dir * ((size_t)BDIM * LDIM * G3);
    float* __restrict__ hglob = g_h + (size_t)dir * 2 * HDIM * BDIM;

    // ws2[c][k] = (w, w), c = rr*3+g
    for (int idx = tid; idx < 24 * 512; idx += 256) {
        const int c = idx >> 9, k = idx & 511;
        const int rr = c / 3, g = c - 3 * rr;
        const float w = whh[(size_t)(g * HDIM + j0 + rr) * HDIM + k];
        ws2[c * 512 + k] = make_float2(w, w);
    }
    const float bh_r = bhh[j0 + rg];
    const float bh_z = bhh[HDIM + j0 + rg];
    const float bh_n = bhh[2 * HDIM + j0 + rg];

    float hp0 = 0.0f, hp1 = 0.0f;
    *(float2*)&hglob[(size_t)(j0 + rg) * BDIM + b0] = make_float2(0.0f, 0.0f);

    size_t gx_const[6]; int gx_sidx[6];
    #pragma unroll
    for (int i = 0; i < 6; ++i) {
        const int e = tid + i * 256, b = e / 24, c = e - 24 * b;
        const int seg = c >> 3, u = c & 7;
        gx_const[i] = (size_t)b * LDIM * G3 + (size_t)seg * HDIM + j0 + u;
        gx_sidx[i]  = b * 24 + u * 3 + seg;
    }
    const int    ob = tid >> 2;
    const int    ou = (tid & 3) * 2;
    const size_t out_const = (size_t)ob * LDIM * 2 * HDIM + (size_t)dir * HDIM + j0 + ou;

    grid_barrier();

    for (int s = 0; s < LDIM; ++s) {
        const int cur = s & 1, nxt = cur ^ 1;
        const int t_in = dir ? (LDIM - 1 - s) : s;
        const float* __restrict__ hsrc = hglob + (size_t)cur * HDIM * BDIM;

        float gxr[6];
        #pragma unroll
        for (int i = 0; i < 6; ++i)
            gxr[i] = gxbase[gx_const[i] + (size_t)t_in * G3];

        float4 hreg[8];
        #pragma unroll
        for (int i = 0; i < 8; ++i)
            hreg[i] = *(const float4*)(hsrc + (tid + i * 256) * 4);

        #pragma unroll
        for (int i = 0; i < 6; ++i) gxs[gx_sidx[i]] = gxr[i];
        #pragma unroll
        for (int i = 0; i < 8; ++i)
            *(float4*)(hsS + (tid + i * 256) * 4) = hreg[i];
        __syncthreads();

        u64 accr = pack2(bh_r);
        u64 accz = pack2(bh_z);
        u64 accn = pack2(bh_n);

        #pragma unroll 1
        for (int c4 = 0; c4 < 4; ++c4) {
            if (c4 < 3) {
                const float* src = hsrc + (c4 + 1) * 8192;
                #pragma unroll
                for (int i = 0; i < 8; ++i)
                    hreg[i] = *(const float4*)(src + (tid + i * 256) * 4);
            }
            const u64* hb = (const u64*)(hsS + (c4 & 1) * 8192);
            const float2* wbase = ws2 + (rg * 3) * 512 + c4 * 128;
            const ulonglong2* wrp = (const ulonglong2*)(wbase);
            const ulonglong2* wzp = (const ulonglong2*)(wbase + 512);
            const ulonglong2* wnp = (const ulonglong2*)(wbase + 1024);
            #pragma unroll 4
            for (int k = 0; k < 128; k += 4) {
                const u64 h0 = hb[(k + 0) * 32 + bg];
                const u64 h1 = hb[(k + 1) * 32 + bg];
                const u64 h2 = hb[(k + 2) * 32 + bg];
                const u64 h3 = hb[(k + 3) * 32 + bg];
                const ulonglong2 wra = wrp[(k >> 1)];
                const ulonglong2 wrb = wrp[(k >> 1) + 1];
                const ulonglong2 wza = wzp[(k >> 1)];
                const ulonglong2 wzb = wzp[(k >> 1) + 1];
                const ulonglong2 wna = wnp[(k >> 1)];
                const ulonglong2 wnb = wnp[(k >> 1) + 1];
                fma2(accr, wra.x, h0); fma2(accr, wra.y, h1);
                fma2(accr, wrb.x, h2); fma2(accr, wrb.y, h3);
                fma2(accz, wza.x, h0); fma2(accz, wza.y, h1);
                fma2(accz, wzb.x, h2); fma2(accz, wzb.y, h3);
                fma2(accn, wna.x, h0); fma2(accn, wna.y, h1);
                fma2(accn, wnb.x, h2); fma2(accn, wnb.y, h3);
            }
            if (c4 < 3) {
                float* dst = hsS + ((c4 + 1) & 1) * 8192;
                #pragma unroll
                for (int i = 0; i < 8; ++i)
                    *(float4*)(dst + (tid + i * 256) * 4) = hreg[i];
            }
            __syncthreads();
        }

        const float2 arv = unpack2(accr);
        const float2 azv = unpack2(accz);
        const float2 anv = unpack2(accn);

        const float mk0 = feats_mask[(size_t)b0 * LDIM + t_in];
        const float mk1 = feats_mask[(size_t)(b0 + 1) * LDIM + t_in];
        const float* gx0 = gxs + b0 * 24 + rg * 3;
        const float* gx1 = gxs + (b0 + 1) * 24 + rg * 3;

        const float r0 = sigf(gx0[0] + arv.x);
        const float z0 = sigf(gx0[1] + azv.x);
        const float n0v = tanhf(gx0[2] + r0 * anv.x);
        float hn0 = (1.0f - z0) * n0v + z0 * hp0;
        hn0 = mk0 * hn0 + (1.0f - mk0) * hp0;

        const float r1 = sigf(gx1[0] + arv.y);
        const float z1 = sigf(gx1[1] + azv.y);
        const float n1v = tanhf(gx1[2] + r1 * anv.y);
        float hn1 = (1.0f - z1) * n1v + z1 * hp1;
        hn1 = mk1 * hn1 + (1.0f - mk1) * hp1;

        hp0 = hn0; hp1 = hn1;
        *(float2*)&hglob[(size_t)(nxt * HDIM + j0 + rg) * BDIM + b0] = make_float2(hn0, hn1);
        outs[b0 * 8 + rg]       = hn0;
        outs[(b0 + 1) * 8 + rg] = hn1;
        __syncthreads();

        float2 ov = *(const float2*)(outs + ob * 8 + ou);
        *(float2*)(out + out_const + (size_t)t_in * 2 * HDIM) = ov;

        grid_barrier();
    }
}

// =====================================================================
extern "C" void kernel_launch(void* const* d_in, const int* in_sizes, int n_in,
                              void* d_out, int out_size)
{
    const float* feats      = (const float*)d_in[0];
    const float* feats_mask = (const float*)d_in[1];
    const float* w_ih_lr    = (const float*)d_in[2];
    const float* w_hh_lr    = (const float*)d_in[3];
    const float* b_ih_lr    = (const float*)d_in[4];
    const float* b_hh_lr    = (const float*)d_in[5];
    const float* w_ih_rl    = (const float*)d_in[6];
    const float* w_hh_rl    = (const float*)d_in[7];
    const float* b_ih_rl    = (const float*)d_in[8];
    const float* b_hh_rl    = (const float*)d_in[9];
    float* out = (float*)d_out;

    cudaFuncSetAttribute(scan_kernel, cudaFuncAttributeMaxDynamicSharedMemorySize,
                         SM_FLOATS * (int)sizeof(float));

    convx_kernel<<<32768, 256>>>(feats);
    convw_kernel<<<1536, 256>>>(w_ih_lr, w_ih_rl);

    dim3 ggrid(G3 / 128, (BDIM * LDIM) / 128, 2);
    hgemm_kernel<<<ggrid, 256>>>(b_ih_lr, b_ih_rl);

    scan_kernel<<<NCTA, 256, SM_FLOATS * sizeof(float)>>>(
        feats_mask, w_hh_lr, b_hh_lr, w_hh_rl, b_hh_rl, out);
}

// round 8
// speedup vs baseline: 1.3459x; 1.3459x over previous
#include <cuda_runtime.h>
#include <cuda_bf16.h>
#include <math.h>

#define BDIM   64
#define LDIM   1024
#define INDIM  512
#define HDIM   512
#define G3     1536
#define NCTA   128
#define HS     8

typedef unsigned long long u64;

// ---------- static device scratch (no allocations) ----------
__device__ float g_gx[(size_t)2 * BDIM * LDIM * G3];          // [dir][b][l][1536] fp32
__device__ __nv_bfloat16 g_xb[(size_t)BDIM * LDIM * 1536];    // A' = [hi|hi|lo]
__device__ __nv_bfloat16 g_wb[(size_t)2 * 1536 * 1536];       // B' = [hi|lo|hi] per dir
__device__ unsigned g_hx[2 * 2 * BDIM * HDIM];                // [dir][buf][b][k] bf16 hi|lo
__device__ unsigned g_ticket;                                 // monotonic barrier counter

// =====================================================================
// helpers
// =====================================================================
__device__ __forceinline__ unsigned pack_bf16x2(float a, float b)
{
    unsigned lo = (unsigned)__bfloat16_as_ushort(__float2bfloat16(a));
    unsigned hi = (unsigned)__bfloat16_as_ushort(__float2bfloat16(b));
    return lo | (hi << 16);
}
__device__ __forceinline__ float bf16_hi(float v)
{
    return __bfloat162float(__float2bfloat16(v));
}
__device__ __forceinline__ unsigned prmt(unsigned a, unsigned b, unsigned sel)
{
    unsigned d;
    asm("prmt.b32 %0, %1, %2, %3;" : "=r"(d) : "r"(a), "r"(b), "r"(sel));
    return d;
}

__global__ void convx_kernel(const float* __restrict__ X)
{
    const size_t i = (size_t)blockIdx.x * 256 + threadIdx.x;   // < 8388608
    float4 v = ((const float4*)X)[i];
    const size_t m  = i >> 7;
    const int    kq = (int)(i & 127);
    uint2 h, l;
    h.x = pack_bf16x2(v.x, v.y);
    h.y = pack_bf16x2(v.z, v.w);
    l.x = pack_bf16x2(v.x - bf16_hi(v.x), v.y - bf16_hi(v.y));
    l.y = pack_bf16x2(v.z - bf16_hi(v.z), v.w - bf16_hi(v.w));
    __nv_bfloat16* d = g_xb + m * 1536 + kq * 4;
    *(uint2*)(d)        = h;
    *(uint2*)(d + 512)  = h;
    *(uint2*)(d + 1024) = l;
}

__global__ void convw_kernel(const float* __restrict__ Wlr, const float* __restrict__ Wrl)
{
    const int i   = blockIdx.x * 256 + threadIdx.x;            // < 393216
    const int dir = i / 196608;
    const int rem = i - dir * 196608;
    const int n   = rem >> 7;
    const int kq  = rem & 127;
    const float* W = dir ? Wrl : Wlr;
    float4 v = ((const float4*)W)[rem];
    uint2 h, l;
    h.x = pack_bf16x2(v.x, v.y);
    h.y = pack_bf16x2(v.z, v.w);
    l.x = pack_bf16x2(v.x - bf16_hi(v.x), v.y - bf16_hi(v.y));
    l.y = pack_bf16x2(v.z - bf16_hi(v.z), v.w - bf16_hi(v.w));
    __nv_bfloat16* d = g_wb + (size_t)dir * 1536 * 1536 + (size_t)n * 1536 + kq * 4;
    *(uint2*)(d)        = h;
    *(uint2*)(d + 512)  = l;
    *(uint2*)(d + 1024) = h;
}

// =====================================================================
// mma primitives (proven in hgemm)
// =====================================================================
__device__ __forceinline__ void ldsm4(unsigned& r0, unsigned& r1, unsigned& r2, unsigned& r3,
                                      const void* p)
{
    unsigned a = (unsigned)__cvta_generic_to_shared(p);
    asm volatile("ldmatrix.sync.aligned.m8n8.x4.shared.b16 {%0,%1,%2,%3}, [%4];"
                 : "=r"(r0), "=r"(r1), "=r"(r2), "=r"(r3) : "r"(a));
}
__device__ __forceinline__ void mma16816(float* c, const unsigned* a, unsigned b0, unsigned b1)
{
    asm volatile("mma.sync.aligned.m16n8k16.row.col.f32.bf16.bf16.f32 "
                 "{%0,%1,%2,%3}, {%4,%5,%6,%7}, {%8,%9}, {%0,%1,%2,%3};"
                 : "+f"(c[0]), "+f"(c[1]), "+f"(c[2]), "+f"(c[3])
                 : "r"(a[0]), "r"(a[1]), "r"(a[2]), "r"(a[3]), "r"(b0), "r"(b1));
}

// =====================================================================
// Input-projection GEMM (unchanged, passed R7)
// =====================================================================
__global__ void __launch_bounds__(256, 1)
hgemm_kernel(const float* __restrict__ blr, const float* __restrict__ brl)
{
    __shared__ __nv_bfloat16 As[2][128][40];
    __shared__ __nv_bfloat16 Bs[2][128][40];

    const int tid  = threadIdx.x;
    const int lane = tid & 31;
    const int wid  = tid >> 5;
    const int dir  = blockIdx.z;
    const int m0   = blockIdx.y * 128;
    const int n0   = blockIdx.x * 128;
    const int wm   = wid >> 1;
    const int wn   = wid & 1;

    const int row0 = tid >> 2;
    const int cc   = tid & 3;

    const __nv_bfloat16* ga0 = g_xb + (size_t)(m0 + row0) * 1536 + cc * 8;
    const __nv_bfloat16* gb0 = g_wb + (size_t)dir * 1536 * 1536
                                    + (size_t)(n0 + row0) * 1536 + cc * 8;

    uint4 av0 = *(const uint4*)ga0;
    uint4 av1 = *(const uint4*)(ga0 + (size_t)64 * 1536);
    uint4 bv0 = *(const uint4*)gb0;
    uint4 bv1 = *(const uint4*)(gb0 + (size_t)64 * 1536);
    *(uint4*)&As[0][row0][cc * 8]      = av0;
    *(uint4*)&As[0][row0 + 64][cc * 8] = av1;
    *(uint4*)&Bs[0][row0][cc * 8]      = bv0;
    *(uint4*)&Bs[0][row0 + 64][cc * 8] = bv1;
    __syncthreads();

    float acc[2][8][4];
    #pragma unroll
    for (int mt = 0; mt < 2; ++mt)
        #pragma unroll
        for (int nt = 0; nt < 8; ++nt)
            #pragma unroll
            for (int q = 0; q < 4; ++q) acc[mt][nt][q] = 0.0f;

    #pragma unroll 1
    for (int kt = 0; kt < 48; ++kt) {
        const int buf = kt & 1;
        if (kt < 47) {
            const int off = (kt + 1) * 32;
            av0 = *(const uint4*)(ga0 + off);
            av1 = *(const uint4*)(ga0 + (size_t)64 * 1536 + off);
            bv0 = *(const uint4*)(gb0 + off);
            bv1 = *(const uint4*)(gb0 + (size_t)64 * 1536 + off);
        }
        #pragma unroll
        for (int ks = 0; ks < 2; ++ks) {
            unsigned af[2][4], bfr[4][4];
            #pragma unroll
            for (int mt = 0; mt < 2; ++mt)
                ldsm4(af[mt][0], af[mt][1], af[mt][2], af[mt][3],
                      &As[buf][wm * 32 + mt * 16 + (lane & 15)][ks * 16 + (lane >> 4) * 8]);
            #pragma unroll
            for (int nt2 = 0; nt2 < 4; ++nt2)
                ldsm4(bfr[nt2][0], bfr[nt2][1], bfr[nt2][2], bfr[nt2][3],
                      &Bs[buf][wn * 64 + nt2 * 16 + (lane & 15)][ks * 16 + (lane >> 4) * 8]);
            #pragma unroll
            for (int mt = 0; mt < 2; ++mt)
                #pragma unroll
                for (int nt = 0; nt < 8; ++nt)
                    mma16816(acc[mt][nt], af[mt],
                             bfr[nt >> 1][nt & 1], bfr[nt >> 1][2 + (nt & 1)]);
        }
        if (kt < 47) {
            const int nb = buf ^ 1;
            *(uint4*)&As[nb][row0][cc * 8]      = av0;
            *(uint4*)&As[nb][row0 + 64][cc * 8] = av1;
            *(uint4*)&Bs[nb][row0][cc * 8]      = bv0;
            *(uint4*)&Bs[nb][row0 + 64][cc * 8] = bv1;
        }
        __syncthreads();
    }

    const float* bia = dir ? brl : blr;
    float* C = g_gx + (size_t)dir * ((size_t)BDIM * LDIM * G3);
    #pragma unroll
    for (int mt = 0; mt < 2; ++mt) {
        #pragma unroll
        for (int nt = 0; nt < 8; ++nt) {
            const int r  = m0 + wm * 32 + mt * 16 + (lane >> 2);
            const int nc = n0 + wn * 64 + nt * 8 + (lane & 3) * 2;
            const float bx = bia[nc], by = bia[nc + 1];
            float* Cp = C + (size_t)r * G3 + nc;
            *(float2*)Cp = make_float2(acc[mt][nt][0] + bx, acc[mt][nt][1] + by);
            *(float2*)(Cp + (size_t)8 * G3) =
                make_float2(acc[mt][nt][2] + bx, acc[mt][nt][3] + by);
        }
    }
}

// =====================================================================
// Tensor-core recurrent scan. 128 CTAs (64/dir) x 256 threads.
// CTA owns 8 hidden units (24 gate-cols). Per step:
//   stage h (bf16 hi|lo) from global into Ahi/Alo smem,
//   G[64,24] = Ahi@Whi + Ahi@Wlo + Alo@Whi  (mma, fp32 acc),
//   warps: 4 m-tiles x 2 k-halves, partials reduced via smem,
//   fp32 gates, h_prev in regs, h_new packed back to global.
// =====================================================================
#define APITCH  1040                 // (512+8) bf16 * 2B, ldsm conflict-free
#define OFF_AHI 0
#define OFF_ALO 66560
#define OFF_BHI 133120
#define OFF_BLO 166400
#define OFF_RED 199680               // float[2*64*26]
#define OFF_OUTS 212992              // float[512]
#define OFF_OHX  215040              // unsigned[512]
#define SM_BYTES 217088

__device__ __forceinline__ void grid_barrier()
{
    __syncthreads();
    if (threadIdx.x == 0) {
        __threadfence();
        unsigned t = atomicAdd(&g_ticket, 1u);
        unsigned target = (t / NCTA + 1u) * NCTA;
        while ((int)(*(volatile unsigned*)&g_ticket - target) < 0) { }
        __threadfence();
    }
    __syncthreads();
}

__device__ __forceinline__ float sigf(float x) { return 1.0f / (1.0f + __expf(-x)); }
__device__ __forceinline__ float tanhfast(float x) { return 2.0f * sigf(2.0f * x) - 1.0f; }

__global__ void __launch_bounds__(256, 1)
scan_kernel(const float* __restrict__ feats_mask,
            const float* __restrict__ whh_lr, const float* __restrict__ bhh_lr,
            const float* __restrict__ whh_rl, const float* __restrict__ bhh_rl,
            float* __restrict__ out)
{
    extern __shared__ char smem[];
    char*     Ahi  = smem + OFF_AHI;
    char*     Alo  = smem + OFF_ALO;
    char*     Bhi  = smem + OFF_BHI;
    char*     Blo  = smem + OFF_BLO;
    float*    redF = (float*)(smem + OFF_RED);
    float*    outs = (float*)(smem + OFF_OUTS);
    unsigned* ohx  = (unsigned*)(smem + OFF_OHX);

    const int tid   = threadIdx.x;
    const int lane  = tid & 31;
    const int wid   = tid >> 5;
    const int dir   = blockIdx.x >> 6;
    const int slice = blockIdx.x & 63;
    const int j0    = slice * HS;
    const int wm    = wid >> 1;          // m-tile 0..3
    const int wk    = wid & 1;           // k-half 0..1

    const float* __restrict__ whh = dir ? whh_rl : whh_lr;
    const float* __restrict__ bhh = dir ? bhh_rl : bhh_lr;
    const float* __restrict__ gxbase = g_gx + (size_t)dir * ((size_t)BDIM * LDIM * G3);
    unsigned* __restrict__ hx = g_hx + (size_t)dir * 2 * BDIM * HDIM;

    // ---- build W-split tiles (once): Bhi/Blo[c][k], c = g*8 + u ----
    for (int idx = tid; idx < 6144; idx += 256) {
        const int c = idx >> 8, kp = idx & 255, k = kp * 2;
        const int g = c >> 3, u = c & 7;
        const float* wr = whh + (size_t)(g * HDIM + j0 + u) * HDIM + k;
        const float w0 = wr[0], w1 = wr[1];
        const float h0 = bf16_hi(w0), h1 = bf16_hi(w1);
        *(unsigned*)(Bhi + c * APITCH + k * 2) = pack_bf16x2(w0, w1);
        *(unsigned*)(Blo + c * APITCH + k * 2) = pack_bf16x2(w0 - h0, w1 - h1);
    }

    // ---- gate-phase thread mapping: unit ub & ub+4, batch bb ----
    const int ub = tid >> 6;             // 0..3
    const int bb = tid & 63;
    float bias[2][3];
    #pragma unroll
    for (int q = 0; q < 2; ++q)
        #pragma unroll
        for (int g = 0; g < 3; ++g)
            bias[q][g] = bhh[g * HDIM + j0 + ub + q * 4];

    // ---- init h state: regs + global hx buffer 0 ----
    float hp0 = 0.0f, hp1 = 0.0f;        // h_prev for (ub,bb), (ub+4,bb)
    for (int idx = tid; idx < 512; idx += 256) {
        const int b = idx >> 3, u = idx & 7;
        hx[(size_t)b * HDIM + j0 + u] = 0u;   // buf 0
    }

    // staging map: thread covers row bsrow, k-range [kq*128, +128)
    const int bsrow = tid & 63;
    const int kq    = tid >> 6;

    const int ob = tid >> 2;             // store phase: batch
    const int oq = tid & 3;              // 2-col group

    grid_barrier();

    for (int s = 0; s < LDIM; ++s) {
        const int cur = s & 1, nxt = cur ^ 1;
        const int t_in = dir ? (LDIM - 1 - s) : s;

        // ---- prefetch gx + mask into regs (used in gate phase) ----
        float gxr[2][3];
        #pragma unroll
        for (int q = 0; q < 2; ++q)
            #pragma unroll
            for (int g = 0; g < 3; ++g)
                gxr[q][g] = gxbase[((size_t)bb * LDIM + t_in) * G3
                                   + g * HDIM + j0 + ub + q * 4];
        const float mk = feats_mask[(size_t)bb * LDIM + t_in];

        // ---- stage h: global u32(hi|lo) -> Ahi/Alo bf16 tiles ----
        {
            const unsigned* src = hx + (size_t)cur * BDIM * HDIM
                                     + (size_t)bsrow * HDIM + kq * 128;
            char* dhi = Ahi + bsrow * APITCH + kq * 256;
            char* dlo = Alo + bsrow * APITCH + kq * 256;
            #pragma unroll 4
            for (int i = 0; i < 16; ++i) {
                uint4 r0 = ((const uint4*)src)[i * 2];
                uint4 r1 = ((const uint4*)src)[i * 2 + 1];
                uint4 hi, lo;
                hi.x = prmt(r0.x, r0.y, 0x5410); lo.x = prmt(r0.x, r0.y, 0x7632);
                hi.y = prmt(r0.z, r0.w, 0x5410); lo.y = prmt(r0.z, r0.w, 0x7632);
                hi.z = prmt(r1.x, r1.y, 0x5410); lo.z = prmt(r1.x, r1.y, 0x7632);
                hi.w = prmt(r1.z, r1.w, 0x5410); lo.w = prmt(r1.z, r1.w, 0x7632);
                *(uint4*)(dhi + i * 16) = hi;
                *(uint4*)(dlo + i * 16) = lo;
            }
        }
        __syncthreads();

        // ---- mma: G[64,24] partials over this warp's k-half ----
        float acc[3][4];
        #pragma unroll
        for (int nt = 0; nt < 3; ++nt)
            #pragma unroll
            for (int q = 0; q < 4; ++q) acc[nt][q] = 0.0f;

        {
            const int arow = (wm * 16 + (lane & 15)) * APITCH;
            const int brow0 = (lane & 15) * APITCH;
            const int brow1 = (16 + (lane & 15)) * APITCH;
            #pragma unroll 4
            for (int i = 0; i < 16; ++i) {
                const int kb = (wk * 256 + i * 16 + (lane >> 4) * 8) * 2;
                unsigned aH[4], aL[4], bh0[4], bh1[4], bl0[4], bl1[4];
                ldsm4(aH[0], aH[1], aH[2], aH[3], Ahi + arow + kb);
                ldsm4(aL[0], aL[1], aL[2], aL[3], Alo + arow + kb);
                ldsm4(bh0[0], bh0[1], bh0[2], bh0[3], Bhi + brow0 + kb);
                ldsm4(bh1[0], bh1[1], bh1[2], bh1[3], Bhi + brow1 + kb);
                ldsm4(bl0[0], bl0[1], bl0[2], bl0[3], Blo + brow0 + kb);
                ldsm4(bl1[0], bl1[1], bl1[2], bl1[3], Blo + brow1 + kb);
                // ntile0: cols 0-7, ntile1: 8-15, ntile2: 16-23
                mma16816(acc[0], aH, bh0[0], bh0[2]);
                mma16816(acc[0], aH, bl0[0], bl0[2]);
                mma16816(acc[0], aL, bh0[0], bh0[2]);
                mma16816(acc[1], aH, bh0[1], bh0[3]);
                mma16816(acc[1], aH, bl0[1], bl0[3]);
                mma16816(acc[1], aL, bh0[1], bh0[3]);
                mma16816(acc[2], aH, bh1[0], bh1[2]);
                mma16816(acc[2], aH, bl1[0], bl1[2]);
                mma16816(acc[2], aL, bh1[0], bh1[2]);
            }
        }

        // ---- write partials: red[(wk*64 + batch)*26 + col] ----
        {
            const int rA = wk * 64 + wm * 16 + (lane >> 2);
            const int cA = (lane & 3) * 2;
            #pragma unroll
            for (int nt = 0; nt < 3; ++nt) {
                float* p = redF + rA * 26 + nt * 8 + cA;
                p[0] = acc[nt][0]; p[1] = acc[nt][1];
                p[8 * 26] = acc[nt][2]; p[8 * 26 + 1] = acc[nt][3];
            }
        }
        __syncthreads();

        // ---- gates (fp32) for (ub,bb) and (ub+4,bb) ----
        {
            const float* r0 = redF + bb * 26;
            const float* r1 = redF + (64 + bb) * 26;

            const int u0 = ub;
            float ghr = r0[u0] + r1[u0] + bias[0][0];
            float ghz = r0[8 + u0] + r1[8 + u0] + bias[0][1];
            float ghn = r0[16 + u0] + r1[16 + u0] + bias[0][2];
            float rr = sigf(gxr[0][0] + ghr);
            float zz = sigf(gxr[0][1] + ghz);
            float nn = tanhfast(gxr[0][2] + rr * ghn);
            float hn = (1.0f - zz) * nn + zz * hp0;
            hn = mk * hn + (1.0f - mk) * hp0;
            hp0 = hn;
            outs[bb * 8 + u0] = hn;
            ohx[bb * 8 + u0]  = pack_bf16x2(hn, hn - bf16_hi(hn));

            const int u1 = ub + 4;
            ghr = r0[u1] + r1[u1] + bias[1][0];
            ghz = r0[8 + u1] + r1[8 + u1] + bias[1][1];
            ghn = r0[16 + u1] + r1[16 + u1] + bias[1][2];
            rr = sigf(gxr[1][0] + ghr);
            zz = sigf(gxr[1][1] + ghz);
            nn = tanhfast(gxr[1][2] + rr * ghn);
            hn = (1.0f - zz) * nn + zz * hp1;
            hn = mk * hn + (1.0f - mk) * hp1;
            hp1 = hn;
            outs[bb * 8 + u1] = hn;
            ohx[bb * 8 + u1]  = pack_bf16x2(hn, hn - bf16_hi(hn));
        }
        __syncthreads();

        // ---- coalesced stores: out + next-step hx ----
        {
            float2 ov = *(const float2*)(outs + ob * 8 + oq * 2);
            *(float2*)(out + ((size_t)ob * LDIM + t_in) * (2 * HDIM)
                       + dir * HDIM + j0 + oq * 2) = ov;
            uint2 hv = *(const uint2*)(ohx + ob * 8 + oq * 2);
            *(uint2*)(hx + (size_t)nxt * BDIM * HDIM
                      + (size_t)ob * HDIM + j0 + oq * 2) = hv;
        }

        grid_barrier();
    }
}

// =====================================================================
extern "C" void kernel_launch(void* const* d_in, const int* in_sizes, int n_in,
                              void* d_out, int out_size)
{
    const float* feats      = (const float*)d_in[0];
    const float* feats_mask = (const float*)d_in[1];
    const float* w_ih_lr    = (const float*)d_in[2];
    const float* w_hh_lr    = (const float*)d_in[3];
    const float* b_ih_lr    = (const float*)d_in[4];
    const float* b_hh_lr    = (const float*)d_in[5];
    const float* w_ih_rl    = (const float*)d_in[6];
    const float* w_hh_rl    = (const float*)d_in[7];
    const float* b_ih_rl    = (const float*)d_in[8];
    const float* b_hh_rl    = (const float*)d_in[9];
    float* out = (float*)d_out;

    cudaFuncSetAttribute(scan_kernel, cudaFuncAttributeMaxDynamicSharedMemorySize,
                         SM_BYTES);

    convx_kernel<<<32768, 256>>>(feats);
    convw_kernel<<<1536, 256>>>(w_ih_lr, w_ih_rl);

    dim3 ggrid(G3 / 128, (BDIM * LDIM) / 128, 2);
    hgemm_kernel<<<ggrid, 256>>>(b_ih_lr, b_ih_rl);

    scan_kernel<<<NCTA, 256, SM_BYTES>>>(
        feats_mask, w_hh_lr, b_hh_lr, w_hh_rl, b_hh_rl, out);
}